// round 12
// baseline (speedup 1.0000x reference)
#include <cuda_runtime.h>
#include <math.h>

// Pines algorithm, degree N=64, B=65536 — single kernel, one wave.
// R11: w-rescaled Legendre recurrence: b'_l = w_l b_l with w_l = w_{l-2}/n2n_l
// makes the b_{l-2} coefficient exactly 1, removing one packed mul per term:
//   b' = fma2(urho, n1'*b1', rhosq*b2')   (+2 acc fmas)  = 5 packed ops/term.
// n1' and cs/w folded into the smem table (192B per record: 8x8B n1' | 8x16B cs).
// Everything else as R10: 8 pts/thread = 4 f32x2 chains sharing loads, 8-way
// column split across lane-octets (m = 8c+j), 147x448 one wave, shfl combine.

#define N_DEG 64
#define CDIM  67
#define TPB   448
#define NCH   4

typedef unsigned long long u64;

static __constant__ float c_MU   = 398600441800000.0f;
static __constant__ float c_AREF = 6378136.3f;

// 280 records x 192B. offs(c) = records before column-block c.
#define MAIN_BYTES (280 * 192)                    // 53760
#define SEED_OFF   MAIN_BYTES                     // 64 x 48B
#define TAIL_OFF   (SEED_OFF + 3072)              // 24B
#define N2N_OFF    (TAIL_OFF + 24)                // 280*8 floats (raw n2n)
#define DIAG_OFF   (N2N_OFF + 280 * 8 * 4)        // 66 floats
#define SMEM_BYTES (DIAG_OFF + 66 * 4)

__device__ __forceinline__ int offs_c(int c) { return c * (67 - 4 * c); }

// ---------------------------------------------------------------------------
__device__ __forceinline__ u64 fma2(u64 a, u64 b, u64 c) {
    u64 d; asm("fma.rn.f32x2 %0, %1, %2, %3;" : "=l"(d) : "l"(a), "l"(b), "l"(c));
    return d;
}
__device__ __forceinline__ u64 mul2(u64 a, u64 b) {
    u64 d; asm("mul.rn.f32x2 %0, %1, %2;" : "=l"(d) : "l"(a), "l"(b));
    return d;
}
__device__ __forceinline__ u64 add2(u64 a, u64 b) {
    u64 d; asm("add.rn.f32x2 %0, %1, %2;" : "=l"(d) : "l"(a), "l"(b));
    return d;
}
__device__ __forceinline__ u64 pack2(float lo, float hi) {
    u64 d; asm("mov.b64 %0, {%1, %2};" : "=l"(d) : "f"(lo), "f"(hi));
    return d;
}
__device__ __forceinline__ void unpack2(u64 v, float& lo, float& hi) {
    asm("mov.b64 {%0, %1}, %2;" : "=f"(lo), "=f"(hi) : "l"(v));
}
__device__ __forceinline__ u64 dupf(float x) {
    unsigned int b = __float_as_uint(x);
    return ((u64)b << 32) | (u64)b;
}
__device__ __forceinline__ float lo32(u64 v) {
    return __uint_as_float((unsigned int)v);
}

// ---------------------------------------------------------------------------
__global__ void __launch_bounds__(TPB)
pines_kernel(const float4* __restrict__ inp,
             const float*  __restrict__ cBar,
             const float*  __restrict__ sBar,
             float2*       __restrict__ out, int octs)
{
    extern __shared__ char smem[];
    float* s_diag = (float*)(smem + DIAG_OFF);
    float* s_n2n  = (float*)(smem + N2N_OFF);

    int tid = threadIdx.x;

    // ---- diag cumprod (independent per l) ----
    if (tid < 66) {
        int l = tid;
        float d = 1.0f;
        for (int i = 1; i <= l; ++i) {
            float kl   = 2.0f;
            float klm1 = (i == 1) ? 1.0f : 2.0f;
            d *= sqrtf((2.0f * i + 1.0f) * kl / (2.0f * i * klm1));
        }
        s_diag[l] = d;
    }
    __syncthreads();

    // ---- seed records: (c,j) -> {dg,sd},{c0,s0},{c1,s1} (unscaled: w=1) ----
    if (tid < 64) {
        int c = tid >> 3, j = tid & 7;
        int m = 8 * c + j;
        int l1 = m + 1;
        float kl   = 2.0f;
        float klm1 = (l1 == 1) ? 1.0f : 2.0f;
        float sub  = sqrtf(2.0f * l1 * klm1 / kl);
        float dg = s_diag[m];
        float sd = sub * s_diag[m + 1];
        float c0 = cBar[m * CDIM + m];
        float s0 = sBar[m * CDIM + m];
        if (m == 0) { c0 = 0.0f; s0 = 0.0f; }
        float c1 = cBar[(m + 1) * CDIM + m];
        float s1 = sBar[(m + 1) * CDIM + m];
        ulonglong2* sp = (ulonglong2*)(smem + SEED_OFF + tid * 48);
        sp[0] = make_ulonglong2(dupf(dg), dupf(sd));
        sp[1] = make_ulonglong2(dupf(c0), dupf(s0));
        sp[2] = make_ulonglong2(dupf(c1), dupf(s1));
    }
    if (tid == TPB - 1) {   // tail record for m = 64
        u64* tp = (u64*)(smem + TAIL_OFF);
        tp[0] = dupf(cBar[64 * CDIM + 64]);
        tp[1] = dupf(sBar[64 * CDIM + 64]);
        tp[2] = dupf(s_diag[N_DEG]);
    }

    // ---- phase 1: raw table (n1 dup, cs dup, n2n scratch) ----
    for (int t = tid; t < 280 * 8; t += TPB) {
        int e = t >> 3, j = t & 7;
        int c = 0;
        while (c < 7 && e >= offs_c(c + 1)) ++c;
        int k = e - offs_c(c);
        int m = 8 * c + j;
        int l = m + 2 + k;
        float n1 = 0.0f, n2n = 0.0f, cc = 0.0f, ss = 0.0f;
        if (l <= N_DEG) {
            float fl = (float)l, fm = (float)m;
            n1  = sqrtf((2.0f * fl + 1.0f) * (2.0f * fl - 1.0f) /
                        ((fl - fm) * (fl + fm)));
            n2n = -sqrtf((fl + fm - 1.0f) * (2.0f * fl + 1.0f) * (fl - fm - 1.0f) /
                         ((fl + fm) * (fl - fm) * (2.0f * fl - 3.0f)));
            cc = cBar[l * CDIM + m];
            ss = sBar[l * CDIM + m];
        }
        char* rec = smem + e * 192;
        *(u64*)(rec + j * 8) = dupf(n1);
        *(ulonglong2*)(rec + 64 + j * 16) = make_ulonglong2(dupf(cc), dupf(ss));
        s_n2n[e * 8 + j] = n2n;
    }
    __syncthreads();

    // ---- phase 2: per-m walkers apply the w-rescaling in place ----
    // w_l = w_{l-2}/n2n_l  (w_m = w_{m+1} = 1). n1' = n1*w_l/w_{l-1}; cs' = cs/w_l.
    if (tid < 64) {
        int m = tid;
        int c = m >> 3, j = m & 7;
        int e0 = offs_c(c);
        float wm2 = 1.0f, wm1 = 1.0f;
        int nreal = 63 - m;                      // entries with l <= 64
        for (int k = 0; k < nreal; ++k) {
            int e = e0 + k;
            float n2n = s_n2n[e * 8 + j];
            float w   = __fdividef(wm2, n2n);
            char* rec = smem + e * 192;
            u64* pn1 = (u64*)(rec + j * 8);
            float n1p = lo32(*pn1) * __fdividef(w, wm1);
            *pn1 = dupf(n1p);
            ulonglong2* pcs = (ulonglong2*)(rec + 64 + j * 16);
            float iw = __fdividef(1.0f, w);
            ulonglong2 cs = *pcs;
            *pcs = make_ulonglong2(dupf(lo32(cs.x) * iw), dupf(lo32(cs.y) * iw));
            wm2 = wm1; wm1 = w;
        }
    }
    __syncthreads();

    int g = blockIdx.x * TPB + tid;
    int j = g & 7;          // column-set id within the lane-octet
    int q = g >> 3;         // point-octet index
    bool valid = (q < octs);
    if (!valid) q = octs - 1;

    const float4* pv = inp + 8 * q;

    // ---- chain state (4 chains = 8 points) ----
    u64 urho[NCH], rhosq[NCH], rho8[NCH], rm[NCH], acc[NCH];
    u64 cre[NCH], cim[NCH], p8r[NCH], p8i[NCH];
    u64 negone = pack2(-1.0f, -1.0f);

    #pragma unroll
    for (int i = 0; i < NCH; ++i) {
        float4 v0 = pv[2 * i], v1 = pv[2 * i + 1];
        u64 rho = pack2(c_AREF / v0.x, c_AREF / v1.x);
        u64 mu  = pack2(c_MU  / v0.x, c_MU  / v1.x);
        u64 s2  = pack2(v0.y, v1.y);
        u64 t2  = pack2(v0.z, v1.z);
        u64 nt2 = mul2(t2, negone);
        u64 uu  = pack2(v0.w, v1.w);
        urho[i]  = mul2(uu, rho);
        rhosq[i] = mul2(rho, rho);
        u64 rho4 = mul2(rhosq[i], rhosq[i]);
        rho8[i]  = mul2(rho4, rho4);
        u64 p2r = fma2(s2, s2, mul2(nt2, t2));
        u64 st  = mul2(s2, t2);
        u64 p2i = add2(st, st);
        u64 p4r = fma2(p2r, p2r, mul2(mul2(p2i, p2i), negone));
        u64 rr  = mul2(p2r, p2i);
        u64 p4i = add2(rr, rr);
        p8r[i]  = fma2(p4r, p4r, mul2(mul2(p4i, p4i), negone));
        u64 qq  = mul2(p4r, p4i);
        p8i[i]  = add2(qq, qq);
        u64 cr = pack2(1.0f, 1.0f), ci = 0ULL, r = mu;
        for (int it = 0; it < j; ++it) {
            u64 nr = fma2(s2, cr, mul2(nt2, ci));
            u64 ni = fma2(s2, ci, mul2(t2, cr));
            cr = nr; ci = ni;
            r = mul2(r, rho);
        }
        cre[i] = cr; cim[i] = ci; rm[i] = r;
        acc[i] = (j == 0) ? mu : 0ULL;     // MU/r leading term, once
    }

    // ---- column walk: m = 8c + j, c = 0..7 ----
    #pragma unroll 1
    for (int c = 0; c < 8; ++c) {
        const ulonglong2* sp =
            (const ulonglong2*)(smem + SEED_OFF + (c * 8 + j) * 48);
        ulonglong2 dgsd = sp[0], cs0 = sp[1], cs1 = sp[2];

        u64 b1[NCH], b2[NCH], aC[NCH], aS[NCH];
        #pragma unroll
        for (int i = 0; i < NCH; ++i) {
            b2[i] = mul2(rm[i], dgsd.x);                     // l = m
            b1[i] = mul2(mul2(rm[i], urho[i]), dgsd.y);      // l = m+1
            aC[i] = mul2(b2[i], cs0.x);
            aS[i] = mul2(b2[i], cs0.y);
            aC[i] = fma2(b1[i], cs1.x, aC[i]);
            aS[i] = fma2(b1[i], cs1.y, aS[i]);
        }

        const char* p = smem + offs_c(c) * 192;
        const char* pj8  = p + j * 8;
        const char* pj16 = p + 64 + j * 16;
        int n = 63 - 8 * c;                                  // uniform (padded)
        #pragma unroll 2
        for (int k = 0; k < n; ++k) {
            u64        n1p = *(const u64*)(pj8);
            ulonglong2 cs  = *(const ulonglong2*)(pj16);
            pj8 += 192; pj16 += 192;
            #pragma unroll
            for (int i = 0; i < NCH; ++i) {
                u64 m1 = mul2(n1p, b1[i]);
                u64 b  = fma2(urho[i], m1, mul2(rhosq[i], b2[i]));
                aC[i] = fma2(b, cs.x, aC[i]);
                aS[i] = fma2(b, cs.y, aS[i]);
                b2[i] = b1[i];
                b1[i] = b;
            }
        }

        #pragma unroll
        for (int i = 0; i < NCH; ++i) {
            acc[i] = fma2(cre[i], aC[i], acc[i]);
            acc[i] = fma2(cim[i], aS[i], acc[i]);
            u64 nr = fma2(mul2(cim[i], p8i[i]), negone, mul2(cre[i], p8r[i]));
            u64 ni = fma2(cim[i], p8r[i], mul2(cre[i], p8i[i]));
            cre[i] = nr; cim[i] = ni;
            rm[i] = mul2(rm[i], rho8[i]);
        }
    }

    // tail column m = 64 (j==0 lanes are exactly at m=64 now)
    if (j == 0) {
        const u64* tp = (const u64*)(smem + TAIL_OFF);
        u64 c64 = tp[0], s64 = tp[1], dg64 = tp[2];
        #pragma unroll
        for (int i = 0; i < NCH; ++i) {
            u64 b = mul2(rm[i], dg64);
            acc[i] = fma2(cre[i], mul2(b, c64), acc[i]);
            acc[i] = fma2(cim[i], mul2(b, s64), acc[i]);
        }
    }

    // combine 8 column-set partials within each lane-octet
    #pragma unroll
    for (int i = 0; i < NCH; ++i) {
        u64 a = acc[i];
        a = add2(a, __shfl_xor_sync(0xffffffffu, a, 1));
        a = add2(a, __shfl_xor_sync(0xffffffffu, a, 2));
        a = add2(a, __shfl_xor_sync(0xffffffffu, a, 4));
        acc[i] = a;
    }

    if (valid && j == 0) {
        #pragma unroll
        for (int i = 0; i < NCH; ++i) {
            float lo, hi;
            unpack2(acc[i], lo, hi);
            out[4 * q + i] = make_float2(-lo, -hi);
        }
    }
}

// ---------------------------------------------------------------------------
extern "C" void kernel_launch(void* const* d_in, const int* in_sizes, int n_in,
                              void* d_out, int out_size)
{
    const float* inputs = (const float*)d_in[0];  // [B,4] : r,s,t,u
    const float* cBar   = (const float*)d_in[1];  // [67,67]
    const float* sBar   = (const float*)d_in[2];  // [67,67]
    float*       out    = (float*)d_out;          // [B]

    int B    = in_sizes[0] / 4;
    int octs = B / 8;                             // 8192 point-octets

    cudaFuncSetAttribute(pines_kernel,
                         cudaFuncAttributeMaxDynamicSharedMemorySize,
                         SMEM_BYTES);

    int threads_total = octs * 8;                 // 65536
    int blocks = (threads_total + TPB - 1) / TPB; // 147
    pines_kernel<<<blocks, TPB, SMEM_BYTES>>>(
        (const float4*)inputs, cBar, sBar, (float2*)out, octs);
}

// round 13
// speedup vs baseline: 1.0637x; 1.0637x over previous
#include <cuda_runtime.h>
#include <math.h>

// Pines algorithm, degree N=64, B=65536 — single kernel, one wave.
// R13 = R10 structure (8 pts/thread = 4 f32x2 chains sharing loads, 8-way
// column split m = 8c+j across lane-octets, 256B j-interleaved records,
// 147x448 one wave) + explicit register double-buffering of the table
// stream: record k+1 is loaded before computing record k, so the 29-cyc
// LDS latency is hidden behind ~20 fma ops. One zero-padded record (281st)
// makes the last prefetch always legal.

#define N_DEG 64
#define CDIM  67
#define TPB   448
#define NCH   4

typedef unsigned long long u64;

static __constant__ float c_MU   = 398600441800000.0f;
static __constant__ float c_AREF = 6378136.3f;

// main table: 280 (c,k)-records of 256B + 1 padding record.
#define NREC       281
#define MAIN_BYTES (NREC * 256)
#define SEED_OFF   MAIN_BYTES                 // 64 x 48B
#define TAIL_OFF   (SEED_OFF + 3072)          // 24B
#define DIAG_OFF   (TAIL_OFF + 32)            // 66 floats
#define SMEM_BYTES (DIAG_OFF + 66 * 4)

__device__ __forceinline__ int offs_c(int c) { return c * (67 - 4 * c); }

// ---------------------------------------------------------------------------
__device__ __forceinline__ u64 fma2(u64 a, u64 b, u64 c) {
    u64 d; asm("fma.rn.f32x2 %0, %1, %2, %3;" : "=l"(d) : "l"(a), "l"(b), "l"(c));
    return d;
}
__device__ __forceinline__ u64 mul2(u64 a, u64 b) {
    u64 d; asm("mul.rn.f32x2 %0, %1, %2;" : "=l"(d) : "l"(a), "l"(b));
    return d;
}
__device__ __forceinline__ u64 add2(u64 a, u64 b) {
    u64 d; asm("add.rn.f32x2 %0, %1, %2;" : "=l"(d) : "l"(a), "l"(b));
    return d;
}
__device__ __forceinline__ u64 pack2(float lo, float hi) {
    u64 d; asm("mov.b64 %0, {%1, %2};" : "=l"(d) : "f"(lo), "f"(hi));
    return d;
}
__device__ __forceinline__ void unpack2(u64 v, float& lo, float& hi) {
    asm("mov.b64 {%0, %1}, %2;" : "=f"(lo), "=f"(hi) : "l"(v));
}
__device__ __forceinline__ u64 dupf(float x) {
    unsigned int b = __float_as_uint(x);
    return ((u64)b << 32) | (u64)b;
}

// ---------------------------------------------------------------------------
__global__ void __launch_bounds__(TPB)
pines_kernel(const float4* __restrict__ inp,
             const float*  __restrict__ cBar,
             const float*  __restrict__ sBar,
             float2*       __restrict__ out, int octs)
{
    extern __shared__ char smem[];
    float* s_diag = (float*)(smem + DIAG_OFF);

    int tid = threadIdx.x;

    // ---- diag cumprod (independent per l) ----
    if (tid < 66) {
        int l = tid;
        float d = 1.0f;
        for (int i = 1; i <= l; ++i) {
            float kl   = 2.0f;
            float klm1 = (i == 1) ? 1.0f : 2.0f;
            d *= sqrtf((2.0f * i + 1.0f) * kl / (2.0f * i * klm1));
        }
        s_diag[l] = d;
    }
    __syncthreads();

    // ---- seed records: (c,j) -> {dg,sd},{c0,s0},{c1,s1} ----
    if (tid < 64) {
        int c = tid >> 3, j = tid & 7;
        int m = 8 * c + j;
        int l1 = m + 1;
        float kl   = 2.0f;
        float klm1 = (l1 == 1) ? 1.0f : 2.0f;
        float sub  = sqrtf(2.0f * l1 * klm1 / kl);
        float dg = s_diag[m];
        float sd = sub * s_diag[m + 1];
        float c0 = cBar[m * CDIM + m];
        float s0 = sBar[m * CDIM + m];
        if (m == 0) { c0 = 0.0f; s0 = 0.0f; }       // (0,0) term excluded
        float c1 = cBar[(m + 1) * CDIM + m];
        float s1 = sBar[(m + 1) * CDIM + m];
        ulonglong2* sp = (ulonglong2*)(smem + SEED_OFF + tid * 48);
        sp[0] = make_ulonglong2(dupf(dg), dupf(sd));
        sp[1] = make_ulonglong2(dupf(c0), dupf(s0));
        sp[2] = make_ulonglong2(dupf(c1), dupf(s1));
    }
    if (tid == TPB - 1) {   // tail record for m = 64
        u64* tp = (u64*)(smem + TAIL_OFF);
        tp[0] = dupf(cBar[64 * CDIM + 64]);
        tp[1] = dupf(sBar[64 * CDIM + 64]);
        tp[2] = dupf(s_diag[N_DEG]);
    }

    // ---- main table: 281 records x 8 j-slots (record 280 = zero pad) ----
    for (int t = tid; t < NREC * 8; t += TPB) {
        int e = t >> 3, j = t & 7;
        int c = 0;
        while (c < 7 && e >= offs_c(c + 1)) ++c;
        int k = e - offs_c(c);
        int m = 8 * c + j;
        int l = m + 2 + k;
        float n1 = 0.0f, n2n = 0.0f, cc = 0.0f, ss = 0.0f;
        if (e < 280 && l <= N_DEG) {
            float fl = (float)l, fm = (float)m;
            n1  = sqrtf((2.0f * fl + 1.0f) * (2.0f * fl - 1.0f) /
                        ((fl - fm) * (fl + fm)));
            n2n = -sqrtf((fl + fm - 1.0f) * (2.0f * fl + 1.0f) * (fl - fm - 1.0f) /
                         ((fl + fm) * (fl - fm) * (2.0f * fl - 3.0f)));
            cc = cBar[l * CDIM + m];
            ss = sBar[l * CDIM + m];
        }
        char* rec = smem + e * 256;
        *(ulonglong2*)(rec + j * 16)       = make_ulonglong2(dupf(n1), dupf(n2n));
        *(ulonglong2*)(rec + 128 + j * 16) = make_ulonglong2(dupf(cc), dupf(ss));
    }
    __syncthreads();

    int g = blockIdx.x * TPB + tid;
    int j = g & 7;          // column-set id within the lane-octet
    int q = g >> 3;         // point-octet index
    bool valid = (q < octs);
    if (!valid) q = octs - 1;

    const float4* pv = inp + 8 * q;

    // ---- chain state (4 chains = 8 points) ----
    u64 urho[NCH], rhosq[NCH], rho8[NCH], rm[NCH], acc[NCH];
    u64 cre[NCH], cim[NCH], p8r[NCH], p8i[NCH];
    u64 negone = pack2(-1.0f, -1.0f);

    #pragma unroll
    for (int i = 0; i < NCH; ++i) {
        float4 v0 = pv[2 * i], v1 = pv[2 * i + 1];
        u64 rho = pack2(c_AREF / v0.x, c_AREF / v1.x);
        u64 mu  = pack2(c_MU  / v0.x, c_MU  / v1.x);
        u64 s2  = pack2(v0.y, v1.y);
        u64 t2  = pack2(v0.z, v1.z);
        u64 nt2 = mul2(t2, negone);
        u64 uu  = pack2(v0.w, v1.w);
        urho[i]  = mul2(uu, rho);
        rhosq[i] = mul2(rho, rho);
        u64 rho4 = mul2(rhosq[i], rhosq[i]);
        rho8[i]  = mul2(rho4, rho4);
        // (s+it)^8 by repeated squaring
        u64 p2r = fma2(s2, s2, mul2(nt2, t2));
        u64 st  = mul2(s2, t2);
        u64 p2i = add2(st, st);
        u64 p4r = fma2(p2r, p2r, mul2(mul2(p2i, p2i), negone));
        u64 rr  = mul2(p2r, p2i);
        u64 p4i = add2(rr, rr);
        p8r[i]  = fma2(p4r, p4r, mul2(mul2(p4i, p4i), negone));
        u64 qq  = mul2(p4r, p4i);
        p8i[i]  = add2(qq, qq);
        // start at column m = j
        u64 cr = pack2(1.0f, 1.0f), ci = 0ULL, r = mu;
        for (int it = 0; it < j; ++it) {
            u64 nr = fma2(s2, cr, mul2(nt2, ci));
            u64 ni = fma2(s2, ci, mul2(t2, cr));
            cr = nr; ci = ni;
            r = mul2(r, rho);
        }
        cre[i] = cr; cim[i] = ci; rm[i] = r;
        acc[i] = (j == 0) ? mu : 0ULL;     // MU/r leading term, once
    }

    // ---- column walk: m = 8c + j, c = 0..7 ----
    #pragma unroll 1
    for (int c = 0; c < 8; ++c) {
        const ulonglong2* sp =
            (const ulonglong2*)(smem + SEED_OFF + (c * 8 + j) * 48);
        ulonglong2 dgsd = sp[0], cs0 = sp[1], cs1 = sp[2];

        u64 b1[NCH], b2[NCH], aC[NCH], aS[NCH];
        #pragma unroll
        for (int i = 0; i < NCH; ++i) {
            b2[i] = mul2(rm[i], dgsd.x);                     // l = m
            b1[i] = mul2(mul2(rm[i], urho[i]), dgsd.y);      // l = m+1
            aC[i] = mul2(b2[i], cs0.x);
            aS[i] = mul2(b2[i], cs0.y);
            aC[i] = fma2(b1[i], cs1.x, aC[i]);
            aS[i] = fma2(b1[i], cs1.y, aS[i]);
        }

        const char* p = smem + offs_c(c) * 256 + j * 16;
        int n = 63 - 8 * c;                                  // uniform (padded)

        // software pipeline: load record k, compute record k-1
        ulonglong2 nn_c = *(const ulonglong2*)(p);
        ulonglong2 cs_c = *(const ulonglong2*)(p + 128);
        p += 256;

        #pragma unroll 2
        for (int k = 0; k < n - 1; ++k) {
            ulonglong2 nn_x = *(const ulonglong2*)(p);       // prefetch k+1
            ulonglong2 cs_x = *(const ulonglong2*)(p + 128);
            p += 256;
            #pragma unroll
            for (int i = 0; i < NCH; ++i) {
                u64 t1 = mul2(nn_c.x, b1[i]);
                u64 t2 = mul2(nn_c.y, b2[i]);
                u64 b  = fma2(urho[i], t1, mul2(rhosq[i], t2));
                aC[i] = fma2(b, cs_c.x, aC[i]);
                aS[i] = fma2(b, cs_c.y, aS[i]);
                b2[i] = b1[i];
                b1[i] = b;
            }
            nn_c = nn_x;
            cs_c = cs_x;
        }
        // last record of this column block
        #pragma unroll
        for (int i = 0; i < NCH; ++i) {
            u64 t1 = mul2(nn_c.x, b1[i]);
            u64 t2 = mul2(nn_c.y, b2[i]);
            u64 b  = fma2(urho[i], t1, mul2(rhosq[i], t2));
            aC[i] = fma2(b, cs_c.x, aC[i]);
            aS[i] = fma2(b, cs_c.y, aS[i]);
            b2[i] = b1[i];
            b1[i] = b;
        }

        #pragma unroll
        for (int i = 0; i < NCH; ++i) {
            acc[i] = fma2(cre[i], aC[i], acc[i]);
            acc[i] = fma2(cim[i], aS[i], acc[i]);
            // jump 8 columns: phasor *= (s+it)^8, rm *= rho^8
            u64 nr = fma2(mul2(cim[i], p8i[i]), negone, mul2(cre[i], p8r[i]));
            u64 ni = fma2(cim[i], p8r[i], mul2(cre[i], p8i[i]));
            cre[i] = nr; cim[i] = ni;
            rm[i] = mul2(rm[i], rho8[i]);
        }
    }

    // tail column m = 64 (j==0 lanes are exactly at m=64 now)
    if (j == 0) {
        const u64* tp = (const u64*)(smem + TAIL_OFF);
        u64 c64 = tp[0], s64 = tp[1], dg64 = tp[2];
        #pragma unroll
        for (int i = 0; i < NCH; ++i) {
            u64 b = mul2(rm[i], dg64);
            acc[i] = fma2(cre[i], mul2(b, c64), acc[i]);
            acc[i] = fma2(cim[i], mul2(b, s64), acc[i]);
        }
    }

    // combine 8 column-set partials within each lane-octet
    #pragma unroll
    for (int i = 0; i < NCH; ++i) {
        u64 a = acc[i];
        a = add2(a, __shfl_xor_sync(0xffffffffu, a, 1));
        a = add2(a, __shfl_xor_sync(0xffffffffu, a, 2));
        a = add2(a, __shfl_xor_sync(0xffffffffu, a, 4));
        acc[i] = a;
    }

    if (valid && j == 0) {
        #pragma unroll
        for (int i = 0; i < NCH; ++i) {
            float lo, hi;
            unpack2(acc[i], lo, hi);
            out[4 * q + i] = make_float2(-lo, -hi);
        }
    }
}

// ---------------------------------------------------------------------------
extern "C" void kernel_launch(void* const* d_in, const int* in_sizes, int n_in,
                              void* d_out, int out_size)
{
    const float* inputs = (const float*)d_in[0];  // [B,4] : r,s,t,u
    const float* cBar   = (const float*)d_in[1];  // [67,67]
    const float* sBar   = (const float*)d_in[2];  // [67,67]
    float*       out    = (float*)d_out;          // [B]

    int B    = in_sizes[0] / 4;
    int octs = B / 8;                             // 8192 point-octets

    cudaFuncSetAttribute(pines_kernel,
                         cudaFuncAttributeMaxDynamicSharedMemorySize,
                         SMEM_BYTES);

    int threads_total = octs * 8;                 // 65536
    int blocks = (threads_total + TPB - 1) / TPB; // 147
    pines_kernel<<<blocks, TPB, SMEM_BYTES>>>(
        (const float4*)inputs, cBar, sBar, (float2*)out, octs);
}